// round 5
// baseline (speedup 1.0000x reference)
#include <cuda_runtime.h>

typedef unsigned long long ull;

#define EDIM 768
#define NTOK 16384           // B*S = 2*8192
#define SEQ 8192
#define NH 12
#define HD 64

// ---------------- scratch (device globals; no allocation allowed) ----------------
__device__ __align__(16) float g_q[NTOK * EDIM];
__device__ __align__(16) float g_k[NTOK * EDIM];
__device__ __align__(16) float g_v[NTOK * EDIM];
__device__ __align__(16) float g_x[NTOK * EDIM];

// ---------------- packed f32x2 helpers (FFMA2 path on sm_103a) ----------------
__device__ __forceinline__ void ffma2(ull& d, ull a, ull b) {
    asm("fma.rn.f32x2 %0, %1, %2, %0;" : "+l"(d) : "l"(a), "l"(b));
}
__device__ __forceinline__ void fmul2(ull& d, ull a) {
    asm("mul.rn.f32x2 %0, %0, %1;" : "+l"(d) : "l"(a));
}
__device__ __forceinline__ ull pk2(float x, float y) {
    ull r; asm("mov.b64 %0, {%1, %2};" : "=l"(r) : "f"(x), "f"(y)); return r;
}
__device__ __forceinline__ float2 up2(ull v) {
    float2 f; asm("mov.b64 {%0, %1}, %2;" : "=f"(f.x), "=f"(f.y) : "l"(v)); return f;
}

// ---------------- zero fill of attention output buffer ----------------
__global__ void zero_x_kernel() {
    int i = blockIdx.x * blockDim.x + threadIdx.x;
    reinterpret_cast<float4*>(g_x)[i] = make_float4(0.f, 0.f, 0.f, 0.f);
}

// ---------------- GEMM (NT): C[M,768] = A[M,768] @ W[768,768]^T + bias ----------------
// tile 128x128, K-step 16, 256 threads, 8x8 micro-tile per thread, f32x2 FMAs.
__global__ void __launch_bounds__(256, 2)
gemm_nt(const float* __restrict__ A, const float* __restrict__ W,
        const float* __restrict__ bias, float* __restrict__ C) {
    __shared__ float As[16 * 132];   // As[k][m] transposed
    __shared__ float Bs[16 * 132];   // Bs[k][n] transposed

    const int tid = threadIdx.x;
    const int m0 = blockIdx.y << 7;
    const int n0 = blockIdx.x << 7;
    const int tx = tid & 15;         // 16 col groups
    const int ty = tid >> 4;         // 16 row groups

    ull acc[8][4];
#pragma unroll
    for (int i = 0; i < 8; i++)
#pragma unroll
        for (int jp = 0; jp < 4; jp++) acc[i][jp] = 0ULL;

    const int lrow = tid >> 2;            // 0..63
    const int lcol = (tid & 3) << 2;      // 0,4,8,12
    const float* Ab = A + (size_t)(m0 + lrow) * EDIM + lcol;
    const float* Wb = W + (size_t)(n0 + lrow) * EDIM + lcol;

    for (int k0 = 0; k0 < EDIM; k0 += 16) {
        float4 a0 = *reinterpret_cast<const float4*>(Ab + k0);
        float4 a1 = *reinterpret_cast<const float4*>(Ab + k0 + (size_t)64 * EDIM);
        float4 b0 = *reinterpret_cast<const float4*>(Wb + k0);
        float4 b1 = *reinterpret_cast<const float4*>(Wb + k0 + (size_t)64 * EDIM);
        __syncthreads();
        As[(lcol + 0) * 132 + lrow] = a0.x;
        As[(lcol + 1) * 132 + lrow] = a0.y;
        As[(lcol + 2) * 132 + lrow] = a0.z;
        As[(lcol + 3) * 132 + lrow] = a0.w;
        As[(lcol + 0) * 132 + lrow + 64] = a1.x;
        As[(lcol + 1) * 132 + lrow + 64] = a1.y;
        As[(lcol + 2) * 132 + lrow + 64] = a1.z;
        As[(lcol + 3) * 132 + lrow + 64] = a1.w;
        Bs[(lcol + 0) * 132 + lrow] = b0.x;
        Bs[(lcol + 1) * 132 + lrow] = b0.y;
        Bs[(lcol + 2) * 132 + lrow] = b0.z;
        Bs[(lcol + 3) * 132 + lrow] = b0.w;
        Bs[(lcol + 0) * 132 + lrow + 64] = b1.x;
        Bs[(lcol + 1) * 132 + lrow + 64] = b1.y;
        Bs[(lcol + 2) * 132 + lrow + 64] = b1.z;
        Bs[(lcol + 3) * 132 + lrow + 64] = b1.w;
        __syncthreads();
#pragma unroll
        for (int kk = 0; kk < 16; kk++) {
            float a[8];
#pragma unroll
            for (int i = 0; i < 8; i++) a[i] = As[kk * 132 + ty * 8 + i];
            ull bb[4];
#pragma unroll
            for (int jp = 0; jp < 4; jp++)
                bb[jp] = *reinterpret_cast<const ull*>(Bs + kk * 132 + 2 * tx + 32 * jp);
#pragma unroll
            for (int i = 0; i < 8; i++) {
                ull a2 = pk2(a[i], a[i]);
#pragma unroll
                for (int jp = 0; jp < 4; jp++) ffma2(acc[i][jp], a2, bb[jp]);
            }
        }
    }

#pragma unroll
    for (int i = 0; i < 8; i++) {
        const int row = m0 + ty * 8 + i;
#pragma unroll
        for (int jp = 0; jp < 4; jp++) {
            const int col = n0 + 2 * tx + 32 * jp;
            float2 f = up2(acc[i][jp]);
            f.x += bias[col];
            f.y += bias[col + 1];
            *reinterpret_cast<float2*>(C + (size_t)row * EDIM + col) = f;
        }
    }
}

// ---------------- dilated flash attention ----------------
// Groups: (s=2048,r=1,off=0,h0..3) (s=4096,r=2,off=1,h4..7) (s=8192,r=4,off=2,h8..11)
// Each group's effective per-segment length is 2048. One CTA = 64 queries of one
// (b, segment, head). 128 threads; micro-tile 4q x 8k (interleaved-pair columns).
#define ATTN_SMEM ((64 * 65 + 64 * 66 + 64 * 68) * 4)

__global__ void __launch_bounds__(128, 4) attn_kernel() {
    extern __shared__ float sm[];
    float* Qt = sm;                       // [dd][q]  pad 65 (pre-scaled by 1/8)
    float* Kt = sm + 64 * 65;             // [dd][kk] pad 66; aliased as Ps[q][kk]
    float* Vs = sm + 64 * 65 + 64 * 66;   // [kk][dd] pad 68

    const int tid = threadIdx.x;
    int id = blockIdx.x;
    int g;
    if (id < 1024) { g = 0; }
    else if (id < 1536) { g = 1; id -= 1024; }
    else { g = 2; id -= 1536; }
    const int qb = id & 31; id >>= 5;
    const int gh = id & 3;  id >>= 2;
    const int mcnt = 4 >> g;
    const int m = id & (mcnt - 1);
    const int b = id >> (2 - g);
    const int h = g * 4 + gh;
    const int s = 2048 << g;
    const int off = g;                    // off = i % r for all three groups

    const int tx = tid & 7;
    const int ty = tid >> 3;
    const int ty4 = ty * 4;

    // ---- load Q block (scaled by 1/sqrt(64)) ----
    {
        const int tkn = tid >> 1;
        const int ddb = (tid & 1) * 4;
        const int n = m * s + off + ((qb * 64 + tkn) << g);
        const float* rp = g_q + ((size_t)(b * SEQ + n) * NH + h) * HD;
#pragma unroll
        for (int i = 0; i < 8; i++) {
            const int dd = i * 8 + ddb;
            float4 f = *reinterpret_cast<const float4*>(rp + dd);
            Qt[(dd + 0) * 65 + tkn] = f.x * 0.125f;
            Qt[(dd + 1) * 65 + tkn] = f.y * 0.125f;
            Qt[(dd + 2) * 65 + tkn] = f.z * 0.125f;
            Qt[(dd + 3) * 65 + tkn] = f.w * 0.125f;
        }
    }

    float mrun[4], lrun[4];
    ull o2[4][4];
#pragma unroll
    for (int i = 0; i < 4; i++) {
        mrun[i] = -3.0e38f; lrun[i] = 0.f;
#pragma unroll
        for (int jp = 0; jp < 4; jp++) o2[i][jp] = 0ULL;
    }

    for (int kt = 0; kt < 32; kt++) {
        __syncthreads();   // previous tile fully consumed
        // ---- load K (transposed) and V tiles ----
        {
            const int tkn = tid >> 1;
            const int ddb = (tid & 1) * 4;
            const int n = m * s + off + ((kt * 64 + tkn) << g);
            const size_t base = ((size_t)(b * SEQ + n) * NH + h) * HD;
            const float* rk = g_k + base;
            const float* rv = g_v + base;
#pragma unroll
            for (int i = 0; i < 8; i++) {
                const int dd = i * 8 + ddb;
                float4 f = *reinterpret_cast<const float4*>(rk + dd);
                Kt[(dd + 0) * 66 + tkn] = f.x;
                Kt[(dd + 1) * 66 + tkn] = f.y;
                Kt[(dd + 2) * 66 + tkn] = f.z;
                Kt[(dd + 3) * 66 + tkn] = f.w;
                float4 fv = *reinterpret_cast<const float4*>(rv + dd);
                *reinterpret_cast<float4*>(&Vs[tkn * 68 + dd]) = fv;
            }
        }
        __syncthreads();

        // ---- S = Q K^T  (acc packed over key pairs: kk = 2tx + 16jp + {0,1}) ----
        ull s2[4][4];
#pragma unroll
        for (int i = 0; i < 4; i++)
#pragma unroll
            for (int jp = 0; jp < 4; jp++) s2[i][jp] = 0ULL;

#pragma unroll 2
        for (int dd = 0; dd < 64; dd++) {
            const float* qrow = Qt + dd * 65 + ty4;
            float a0 = qrow[0], a1 = qrow[1], a2 = qrow[2], a3 = qrow[3];
            const float* krow = Kt + dd * 66 + 2 * tx;
            ull b0 = *reinterpret_cast<const ull*>(krow);
            ull b1 = *reinterpret_cast<const ull*>(krow + 16);
            ull b2 = *reinterpret_cast<const ull*>(krow + 32);
            ull b3 = *reinterpret_cast<const ull*>(krow + 48);
            ull p0 = pk2(a0, a0), p1 = pk2(a1, a1), p2 = pk2(a2, a2), p3 = pk2(a3, a3);
            ffma2(s2[0][0], p0, b0); ffma2(s2[0][1], p0, b1); ffma2(s2[0][2], p0, b2); ffma2(s2[0][3], p0, b3);
            ffma2(s2[1][0], p1, b0); ffma2(s2[1][1], p1, b1); ffma2(s2[1][2], p1, b2); ffma2(s2[1][3], p1, b3);
            ffma2(s2[2][0], p2, b0); ffma2(s2[2][1], p2, b1); ffma2(s2[2][2], p2, b2); ffma2(s2[2][3], p2, b3);
            ffma2(s2[3][0], p3, b0); ffma2(s2[3][1], p3, b1); ffma2(s2[3][2], p3, b2); ffma2(s2[3][3], p3, b3);
        }

        // ---- online softmax (row reduction across tx lanes: xor 1,2,4) ----
        float p[4][8];
        float al[4];
#pragma unroll
        for (int i = 0; i < 4; i++) {
            float2 f0 = up2(s2[i][0]), f1 = up2(s2[i][1]), f2 = up2(s2[i][2]), f3 = up2(s2[i][3]);
            float tm = fmaxf(fmaxf(fmaxf(f0.x, f0.y), fmaxf(f1.x, f1.y)),
                             fmaxf(fmaxf(f2.x, f2.y), fmaxf(f3.x, f3.y)));
            tm = fmaxf(tm, __shfl_xor_sync(0xffffffffu, tm, 1));
            tm = fmaxf(tm, __shfl_xor_sync(0xffffffffu, tm, 2));
            tm = fmaxf(tm, __shfl_xor_sync(0xffffffffu, tm, 4));
            const float nm = fmaxf(mrun[i], tm);
            p[i][0] = __expf(f0.x - nm); p[i][1] = __expf(f0.y - nm);
            p[i][2] = __expf(f1.x - nm); p[i][3] = __expf(f1.y - nm);
            p[i][4] = __expf(f2.x - nm); p[i][5] = __expf(f2.y - nm);
            p[i][6] = __expf(f3.x - nm); p[i][7] = __expf(f3.y - nm);
            float ps = ((p[i][0] + p[i][1]) + (p[i][2] + p[i][3])) +
                       ((p[i][4] + p[i][5]) + (p[i][6] + p[i][7]));
            ps += __shfl_xor_sync(0xffffffffu, ps, 1);
            ps += __shfl_xor_sync(0xffffffffu, ps, 2);
            ps += __shfl_xor_sync(0xffffffffu, ps, 4);
            al[i] = __expf(mrun[i] - nm);
            lrun[i] = lrun[i] * al[i] + ps;
            mrun[i] = nm;
        }
        __syncthreads();   // all S reads of Kt done before P overwrites it
#pragma unroll
        for (int i = 0; i < 4; i++) {
            ull a2v = pk2(al[i], al[i]);
#pragma unroll
            for (int jp = 0; jp < 4; jp++) {
                fmul2(o2[i][jp], a2v);
                *reinterpret_cast<ull*>(Kt + (ty4 + i) * 66 + 2 * tx + 16 * jp) =
                    pk2(p[i][2 * jp], p[i][2 * jp + 1]);
            }
        }
        __syncthreads();

        // ---- O += P V  (acc packed over dd pairs: dd = 2tx + 16jp + {0,1}) ----
#pragma unroll 2
        for (int kk = 0; kk < 64; kk++) {
            const float* vrow = Vs + kk * 68 + 2 * tx;
            ull v0 = *reinterpret_cast<const ull*>(vrow);
            ull v1 = *reinterpret_cast<const ull*>(vrow + 16);
            ull v2v = *reinterpret_cast<const ull*>(vrow + 32);
            ull v3 = *reinterpret_cast<const ull*>(vrow + 48);
#pragma unroll
            for (int i = 0; i < 4; i++) {
                float pa = Kt[(ty4 + i) * 66 + kk];
                ull pa2 = pk2(pa, pa);
                ffma2(o2[i][0], pa2, v0);
                ffma2(o2[i][1], pa2, v1);
                ffma2(o2[i][2], pa2, v2v);
                ffma2(o2[i][3], pa2, v3);
            }
        }
    }

    // ---- epilogue: O / l / G  scattered back to dilated positions ----
#pragma unroll
    for (int i = 0; i < 4; i++) {
        const float inv = 1.0f / (3.0f * lrun[i]);
        const int n = m * s + off + ((qb * 64 + ty4 + i) << g);
        float* wp = g_x + ((size_t)(b * SEQ + n) * NH + h) * HD;
#pragma unroll
        for (int jp = 0; jp < 4; jp++) {
            float2 f = up2(o2[i][jp]);
            f.x *= inv; f.y *= inv;
            *reinterpret_cast<float2*>(wp + 2 * tx + 16 * jp) = f;
        }
    }
}

// ---------------- LayerNorm (in place on g_x): warp per row ----------------
__global__ void ln_kernel(const float* __restrict__ w, const float* __restrict__ bp) {
    const int row = blockIdx.x * 8 + (threadIdx.x >> 5);
    const int lane = threadIdx.x & 31;
    float* xr = g_x + (size_t)row * EDIM;
    float v[24];
    float sum = 0.f;
#pragma unroll
    for (int t = 0; t < 24; t++) { v[t] = xr[lane + 32 * t]; sum += v[t]; }
#pragma unroll
    for (int mk = 16; mk >= 1; mk >>= 1) sum += __shfl_xor_sync(0xffffffffu, sum, mk);
    const float mu = sum * (1.0f / 768.0f);
    float sq = 0.f;
#pragma unroll
    for (int t = 0; t < 24; t++) { float d = v[t] - mu; sq += d * d; }
#pragma unroll
    for (int mk = 16; mk >= 1; mk >>= 1) sq += __shfl_xor_sync(0xffffffffu, sq, mk);
    const float rstd = rsqrtf(sq * (1.0f / 768.0f) + 1e-5f);
#pragma unroll
    for (int t = 0; t < 24; t++) {
        const int c = lane + 32 * t;
        xr[c] = (v[t] - mu) * rstd * w[c] + bp[c];
    }
}

// ---------------- launch ----------------
extern "C" void kernel_launch(void* const* d_in, const int* in_sizes, int n_in,
                              void* d_out, int out_size) {
    (void)in_sizes; (void)n_in; (void)out_size;
    const float* query = (const float*)d_in[0];
    const float* key   = (const float*)d_in[1];
    const float* value = (const float*)d_in[2];
    const float* qkv_w = (const float*)d_in[3];
    const float* qkv_b = (const float*)d_in[4];
    const float* ln_w  = (const float*)d_in[5];
    const float* ln_b  = (const float*)d_in[6];
    const float* out_w = (const float*)d_in[7];
    const float* out_b = (const float*)d_in[8];
    float* out = (float*)d_out;

    float *pq, *pk, *pv, *px;
    cudaGetSymbolAddress((void**)&pq, g_q);
    cudaGetSymbolAddress((void**)&pk, g_k);
    cudaGetSymbolAddress((void**)&pv, g_v);
    cudaGetSymbolAddress((void**)&px, g_x);

    cudaFuncSetAttribute(attn_kernel, cudaFuncAttributeMaxDynamicSharedMemorySize, ATTN_SMEM);

    zero_x_kernel<<<NTOK * EDIM / 4 / 256, 256>>>();

    dim3 gg(EDIM / 128, NTOK / 128);
    gemm_nt<<<gg, 256>>>(query, qkv_w,                 qkv_b,           pq);
    gemm_nt<<<gg, 256>>>(key,   qkv_w + EDIM * EDIM,     qkv_b + EDIM,    pk);
    gemm_nt<<<gg, 256>>>(value, qkv_w + 2 * EDIM * EDIM, qkv_b + 2 * EDIM, pv);

    attn_kernel<<<1792, 128, ATTN_SMEM>>>();

    ln_kernel<<<NTOK / 8, 256>>>(ln_w, ln_b);

    gemm_nt<<<gg, 256>>>(px, out_w, out_b, out);
}

// round 8
// speedup vs baseline: 1.0010x; 1.0010x over previous
#include <cuda_runtime.h>

typedef unsigned long long ull;

#define EDIM 768
#define NTOK 16384           // B*S = 2*8192
#define SEQ 8192
#define NH 12
#define HD 64

// ---------------- scratch (device globals; no allocation allowed) ----------------
__device__ __align__(16) float g_q[NTOK * EDIM];
__device__ __align__(16) float g_k[NTOK * EDIM];
__device__ __align__(16) float g_v[NTOK * EDIM];
__device__ __align__(16) float g_x[NTOK * EDIM];

// ---------------- packed f32x2 helpers (FFMA2 path on sm_103a) ----------------
__device__ __forceinline__ void ffma2(ull& d, ull a, ull b) {
    asm("fma.rn.f32x2 %0, %1, %2, %0;" : "+l"(d) : "l"(a), "l"(b));
}
__device__ __forceinline__ void fmul2(ull& d, ull a) {
    asm("mul.rn.f32x2 %0, %0, %1;" : "+l"(d) : "l"(a));
}
__device__ __forceinline__ ull pk2(float x, float y) {
    ull r; asm("mov.b64 %0, {%1, %2};" : "=l"(r) : "f"(x), "f"(y)); return r;
}
__device__ __forceinline__ float2 up2(ull v) {
    float2 f; asm("mov.b64 {%0, %1}, %2;" : "=f"(f.x), "=f"(f.y) : "l"(v)); return f;
}

// ---------------- zero fill of attention output buffer ----------------
__global__ void zero_x_kernel() {
    int i = blockIdx.x * blockDim.x + threadIdx.x;
    reinterpret_cast<float4*>(g_x)[i] = make_float4(0.f, 0.f, 0.f, 0.f);
}

// ---------------- GEMM (NT): C[M,768] = A[M,768] @ W[768,768]^T + bias ----------------
// tile 128x128, K-step 16, 256 threads, 8x8 micro-tile per thread, f32x2 FMAs.
__global__ void __launch_bounds__(256, 2)
gemm_nt(const float* __restrict__ A, const float* __restrict__ W,
        const float* __restrict__ bias, float* __restrict__ C) {
    __shared__ float As[16 * 132];   // As[k][m] transposed
    __shared__ float Bs[16 * 132];   // Bs[k][n] transposed

    const int tid = threadIdx.x;
    const int m0 = blockIdx.y << 7;
    const int n0 = blockIdx.x << 7;
    const int tx = tid & 15;         // 16 col groups
    const int ty = tid >> 4;         // 16 row groups

    ull acc[8][4];
#pragma unroll
    for (int i = 0; i < 8; i++)
#pragma unroll
        for (int jp = 0; jp < 4; jp++) acc[i][jp] = 0ULL;

    const int lrow = tid >> 2;            // 0..63
    const int lcol = (tid & 3) << 2;      // 0,4,8,12
    const float* Ab = A + (size_t)(m0 + lrow) * EDIM + lcol;
    const float* Wb = W + (size_t)(n0 + lrow) * EDIM + lcol;

    for (int k0 = 0; k0 < EDIM; k0 += 16) {
        float4 a0 = *reinterpret_cast<const float4*>(Ab + k0);
        float4 a1 = *reinterpret_cast<const float4*>(Ab + k0 + (size_t)64 * EDIM);
        float4 b0 = *reinterpret_cast<const float4*>(Wb + k0);
        float4 b1 = *reinterpret_cast<const float4*>(Wb + k0 + (size_t)64 * EDIM);
        __syncthreads();
        As[(lcol + 0) * 132 + lrow] = a0.x;
        As[(lcol + 1) * 132 + lrow] = a0.y;
        As[(lcol + 2) * 132 + lrow] = a0.z;
        As[(lcol + 3) * 132 + lrow] = a0.w;
        As[(lcol + 0) * 132 + lrow + 64] = a1.x;
        As[(lcol + 1) * 132 + lrow + 64] = a1.y;
        As[(lcol + 2) * 132 + lrow + 64] = a1.z;
        As[(lcol + 3) * 132 + lrow + 64] = a1.w;
        Bs[(lcol + 0) * 132 + lrow] = b0.x;
        Bs[(lcol + 1) * 132 + lrow] = b0.y;
        Bs[(lcol + 2) * 132 + lrow] = b0.z;
        Bs[(lcol + 3) * 132 + lrow] = b0.w;
        Bs[(lcol + 0) * 132 + lrow + 64] = b1.x;
        Bs[(lcol + 1) * 132 + lrow + 64] = b1.y;
        Bs[(lcol + 2) * 132 + lrow + 64] = b1.z;
        Bs[(lcol + 3) * 132 + lrow + 64] = b1.w;
        __syncthreads();
#pragma unroll
        for (int kk = 0; kk < 16; kk++) {
            float a[8];
#pragma unroll
            for (int i = 0; i < 8; i++) a[i] = As[kk * 132 + ty * 8 + i];
            ull bb[4];
#pragma unroll
            for (int jp = 0; jp < 4; jp++)
                bb[jp] = *reinterpret_cast<const ull*>(Bs + kk * 132 + 2 * tx + 32 * jp);
#pragma unroll
            for (int i = 0; i < 8; i++) {
                ull a2 = pk2(a[i], a[i]);
#pragma unroll
                for (int jp = 0; jp < 4; jp++) ffma2(acc[i][jp], a2, bb[jp]);
            }
        }
    }

#pragma unroll
    for (int i = 0; i < 8; i++) {
        const int row = m0 + ty * 8 + i;
#pragma unroll
        for (int jp = 0; jp < 4; jp++) {
            const int col = n0 + 2 * tx + 32 * jp;
            float2 f = up2(acc[i][jp]);
            f.x += bias[col];
            f.y += bias[col + 1];
            *reinterpret_cast<float2*>(C + (size_t)row * EDIM + col) = f;
        }
    }
}

// ---------------- dilated flash attention ----------------
// Groups: (s=2048,r=1,off=0,h0..3) (s=4096,r=2,off=1,h4..7) (s=8192,r=4,off=2,h8..11)
// Each group's effective per-segment length is 2048. One CTA = 64 queries of one
// (b, segment, head). 128 threads; micro-tile 4q x 8k (interleaved-pair columns).
#define ATTN_SMEM ((64 * 65 + 64 * 66 + 64 * 68) * 4)

__global__ void __launch_bounds__(128, 4) attn_kernel() {
    extern __shared__ float sm[];
    float* Qt = sm;                       // [dd][q]  pad 65 (pre-scaled by 1/8)
    float* Kt = sm + 64 * 65;             // [dd][kk] pad 66; aliased as Ps[q][kk]
    float* Vs = sm + 64 * 65 + 64 * 66;   // [kk][dd] pad 68

    const int tid = threadIdx.x;
    int id = blockIdx.x;
    int g;
    if (id < 1024) { g = 0; }
    else if (id < 1536) { g = 1; id -= 1024; }
    else { g = 2; id -= 1536; }
    const int qb = id & 31; id >>= 5;
    const int gh = id & 3;  id >>= 2;
    const int mcnt = 4 >> g;
    const int m = id & (mcnt - 1);
    const int b = id >> (2 - g);
    const int h = g * 4 + gh;
    const int s = 2048 << g;
    const int off = g;                    // off = i % r for all three groups

    const int tx = tid & 7;
    const int ty = tid >> 3;
    const int ty4 = ty * 4;

    // ---- load Q block (scaled by 1/sqrt(64)) ----
    {
        const int tkn = tid >> 1;
        const int ddb = (tid & 1) * 4;
        const int n = m * s + off + ((qb * 64 + tkn) << g);
        const float* rp = g_q + ((size_t)(b * SEQ + n) * NH + h) * HD;
#pragma unroll
        for (int i = 0; i < 8; i++) {
            const int dd = i * 8 + ddb;
            float4 f = *reinterpret_cast<const float4*>(rp + dd);
            Qt[(dd + 0) * 65 + tkn] = f.x * 0.125f;
            Qt[(dd + 1) * 65 + tkn] = f.y * 0.125f;
            Qt[(dd + 2) * 65 + tkn] = f.z * 0.125f;
            Qt[(dd + 3) * 65 + tkn] = f.w * 0.125f;
        }
    }

    float mrun[4], lrun[4];
    ull o2[4][4];
#pragma unroll
    for (int i = 0; i < 4; i++) {
        mrun[i] = -3.0e38f; lrun[i] = 0.f;
#pragma unroll
        for (int jp = 0; jp < 4; jp++) o2[i][jp] = 0ULL;
    }

    for (int kt = 0; kt < 32; kt++) {
        __syncthreads();   // previous tile fully consumed
        // ---- load K (transposed) and V tiles ----
        {
            const int tkn = tid >> 1;
            const int ddb = (tid & 1) * 4;
            const int n = m * s + off + ((kt * 64 + tkn) << g);
            const size_t base = ((size_t)(b * SEQ + n) * NH + h) * HD;
            const float* rk = g_k + base;
            const float* rv = g_v + base;
#pragma unroll
            for (int i = 0; i < 8; i++) {
                const int dd = i * 8 + ddb;
                float4 f = *reinterpret_cast<const float4*>(rk + dd);
                Kt[(dd + 0) * 66 + tkn] = f.x;
                Kt[(dd + 1) * 66 + tkn] = f.y;
                Kt[(dd + 2) * 66 + tkn] = f.z;
                Kt[(dd + 3) * 66 + tkn] = f.w;
                float4 fv = *reinterpret_cast<const float4*>(rv + dd);
                *reinterpret_cast<float4*>(&Vs[tkn * 68 + dd]) = fv;
            }
        }
        __syncthreads();

        // ---- S = Q K^T  (acc packed over key pairs: kk = 2tx + 16jp + {0,1}) ----
        ull s2[4][4];
#pragma unroll
        for (int i = 0; i < 4; i++)
#pragma unroll
            for (int jp = 0; jp < 4; jp++) s2[i][jp] = 0ULL;

#pragma unroll 2
        for (int dd = 0; dd < 64; dd++) {
            const float* qrow = Qt + dd * 65 + ty4;
            float a0 = qrow[0], a1 = qrow[1], a2 = qrow[2], a3 = qrow[3];
            const float* krow = Kt + dd * 66 + 2 * tx;
            ull b0 = *reinterpret_cast<const ull*>(krow);
            ull b1 = *reinterpret_cast<const ull*>(krow + 16);
            ull b2 = *reinterpret_cast<const ull*>(krow + 32);
            ull b3 = *reinterpret_cast<const ull*>(krow + 48);
            ull p0 = pk2(a0, a0), p1 = pk2(a1, a1), p2 = pk2(a2, a2), p3 = pk2(a3, a3);
            ffma2(s2[0][0], p0, b0); ffma2(s2[0][1], p0, b1); ffma2(s2[0][2], p0, b2); ffma2(s2[0][3], p0, b3);
            ffma2(s2[1][0], p1, b0); ffma2(s2[1][1], p1, b1); ffma2(s2[1][2], p1, b2); ffma2(s2[1][3], p1, b3);
            ffma2(s2[2][0], p2, b0); ffma2(s2[2][1], p2, b1); ffma2(s2[2][2], p2, b2); ffma2(s2[2][3], p2, b3);
            ffma2(s2[3][0], p3, b0); ffma2(s2[3][1], p3, b1); ffma2(s2[3][2], p3, b2); ffma2(s2[3][3], p3, b3);
        }

        // ---- online softmax (row reduction across tx lanes: xor 1,2,4) ----
        float p[4][8];
        float al[4];
#pragma unroll
        for (int i = 0; i < 4; i++) {
            float2 f0 = up2(s2[i][0]), f1 = up2(s2[i][1]), f2 = up2(s2[i][2]), f3 = up2(s2[i][3]);
            float tm = fmaxf(fmaxf(fmaxf(f0.x, f0.y), fmaxf(f1.x, f1.y)),
                             fmaxf(fmaxf(f2.x, f2.y), fmaxf(f3.x, f3.y)));
            tm = fmaxf(tm, __shfl_xor_sync(0xffffffffu, tm, 1));
            tm = fmaxf(tm, __shfl_xor_sync(0xffffffffu, tm, 2));
            tm = fmaxf(tm, __shfl_xor_sync(0xffffffffu, tm, 4));
            const float nm = fmaxf(mrun[i], tm);
            p[i][0] = __expf(f0.x - nm); p[i][1] = __expf(f0.y - nm);
            p[i][2] = __expf(f1.x - nm); p[i][3] = __expf(f1.y - nm);
            p[i][4] = __expf(f2.x - nm); p[i][5] = __expf(f2.y - nm);
            p[i][6] = __expf(f3.x - nm); p[i][7] = __expf(f3.y - nm);
            float ps = ((p[i][0] + p[i][1]) + (p[i][2] + p[i][3])) +
                       ((p[i][4] + p[i][5]) + (p[i][6] + p[i][7]));
            ps += __shfl_xor_sync(0xffffffffu, ps, 1);
            ps += __shfl_xor_sync(0xffffffffu, ps, 2);
            ps += __shfl_xor_sync(0xffffffffu, ps, 4);
            al[i] = __expf(mrun[i] - nm);
            lrun[i] = lrun[i] * al[i] + ps;
            mrun[i] = nm;
        }
        __syncthreads();   // all S reads of Kt done before P overwrites it
#pragma unroll
        for (int i = 0; i < 4; i++) {
            ull a2v = pk2(al[i], al[i]);
#pragma unroll
            for (int jp = 0; jp < 4; jp++) {
                fmul2(o2[i][jp], a2v);
                *reinterpret_cast<ull*>(Kt + (ty4 + i) * 66 + 2 * tx + 16 * jp) =
                    pk2(p[i][2 * jp], p[i][2 * jp + 1]);
            }
        }
        __syncthreads();

        // ---- O += P V  (acc packed over dd pairs: dd = 2tx + 16jp + {0,1}) ----
#pragma unroll 2
        for (int kk = 0; kk < 64; kk++) {
            const float* vrow = Vs + kk * 68 + 2 * tx;
            ull v0 = *reinterpret_cast<const ull*>(vrow);
            ull v1 = *reinterpret_cast<const ull*>(vrow + 16);
            ull v2v = *reinterpret_cast<const ull*>(vrow + 32);
            ull v3 = *reinterpret_cast<const ull*>(vrow + 48);
#pragma unroll
            for (int i = 0; i < 4; i++) {
                float pa = Kt[(ty4 + i) * 66 + kk];
                ull pa2 = pk2(pa, pa);
                ffma2(o2[i][0], pa2, v0);
                ffma2(o2[i][1], pa2, v1);
                ffma2(o2[i][2], pa2, v2v);
                ffma2(o2[i][3], pa2, v3);
            }
        }
    }

    // ---- epilogue: O / l / G  scattered back to dilated positions ----
#pragma unroll
    for (int i = 0; i < 4; i++) {
        const float inv = 1.0f / (3.0f * lrun[i]);
        const int n = m * s + off + ((qb * 64 + ty4 + i) << g);
        float* wp = g_x + ((size_t)(b * SEQ + n) * NH + h) * HD;
#pragma unroll
        for (int jp = 0; jp < 4; jp++) {
            float2 f = up2(o2[i][jp]);
            f.x *= inv; f.y *= inv;
            *reinterpret_cast<float2*>(wp + 2 * tx + 16 * jp) = f;
        }
    }
}

// ---------------- LayerNorm (in place on g_x): warp per row ----------------
__global__ void ln_kernel(const float* __restrict__ w, const float* __restrict__ bp) {
    const int row = blockIdx.x * 8 + (threadIdx.x >> 5);
    const int lane = threadIdx.x & 31;
    float* xr = g_x + (size_t)row * EDIM;
    float v[24];
    float sum = 0.f;
#pragma unroll
    for (int t = 0; t < 24; t++) { v[t] = xr[lane + 32 * t]; sum += v[t]; }
#pragma unroll
    for (int mk = 16; mk >= 1; mk >>= 1) sum += __shfl_xor_sync(0xffffffffu, sum, mk);
    const float mu = sum * (1.0f / 768.0f);
    float sq = 0.f;
#pragma unroll
    for (int t = 0; t < 24; t++) { float d = v[t] - mu; sq += d * d; }
#pragma unroll
    for (int mk = 16; mk >= 1; mk >>= 1) sq += __shfl_xor_sync(0xffffffffu, sq, mk);
    const float rstd = rsqrtf(sq * (1.0f / 768.0f) + 1e-5f);
#pragma unroll
    for (int t = 0; t < 24; t++) {
        const int c = lane + 32 * t;
        xr[c] = (v[t] - mu) * rstd * w[c] + bp[c];
    }
}

// ---------------- launch ----------------
extern "C" void kernel_launch(void* const* d_in, const int* in_sizes, int n_in,
                              void* d_out, int out_size) {
    (void)in_sizes; (void)n_in; (void)out_size;
    const float* query = (const float*)d_in[0];
    const float* key   = (const float*)d_in[1];
    const float* value = (const float*)d_in[2];
    const float* qkv_w = (const float*)d_in[3];
    const float* qkv_b = (const float*)d_in[4];
    const float* ln_w  = (const float*)d_in[5];
    const float* ln_b  = (const float*)d_in[6];
    const float* out_w = (const float*)d_in[7];
    const float* out_b = (const float*)d_in[8];
    float* out = (float*)d_out;

    float *pq, *pk, *pv, *px;
    cudaGetSymbolAddress((void**)&pq, g_q);
    cudaGetSymbolAddress((void**)&pk, g_k);
    cudaGetSymbolAddress((void**)&pv, g_v);
    cudaGetSymbolAddress((void**)&px, g_x);

    cudaFuncSetAttribute(attn_kernel, cudaFuncAttributeMaxDynamicSharedMemorySize, ATTN_SMEM);

    zero_x_kernel<<<NTOK * EDIM / 4 / 256, 256>>>();

    dim3 gg(EDIM / 128, NTOK / 128);
    gemm_nt<<<gg, 256>>>(query, qkv_w,                 qkv_b,           pq);
    gemm_nt<<<gg, 256>>>(key,   qkv_w + EDIM * EDIM,     qkv_b + EDIM,    pk);
    gemm_nt<<<gg, 256>>>(value, qkv_w + 2 * EDIM * EDIM, qkv_b + 2 * EDIM, pv);

    attn_kernel<<<1792, 128, ATTN_SMEM>>>();

    ln_kernel<<<NTOK / 8, 256>>>(ln_w, ln_b);

    gemm_nt<<<gg, 256>>>(px, out_w, out_b, out);
}